// round 4
// baseline (speedup 1.0000x reference)
#include <cuda_runtime.h>

#define BINS 10

// Scratch: global histogram counts (integer => deterministic, exact).
__device__ unsigned int g_counts[BINS];

__global__ void ghm_init_kernel() {
    if (threadIdx.x < BINS) g_counts[threadIdx.x] = 0u;
}

__device__ __forceinline__ int bin_of(float x, float t) {
    // p = sigmoid(x); g = |p - t|; idx = min(floor(10*g), 9)
    float p = __fdividef(1.0f, 1.0f + __expf(-x));
    float g = fabsf(p - t);
    int idx = (int)(g * 10.0f);   // g >= 0, trunc == floor
    return idx > (BINS - 1) ? (BINS - 1) : idx;
}

__device__ __forceinline__ float bce_of(float x, float t) {
    // stable BCE-with-logits: max(x,0) - x*t + log1p(exp(-|x|))
    return fmaxf(x, 0.0f) - x * t + __logf(1.0f + __expf(-fabsf(x)));
}

// ---------------------------------------------------------------------------
// Pass 1: histogram. Lane-spread sub-histograms sh[bin*33 + lane]:
// within a warp all 32 lanes hit DISTINCT addresses -> no intra-warp
// same-address serialization; pad 33 keeps bank conflicts tiny.
// ---------------------------------------------------------------------------
__global__ void __launch_bounds__(512)
ghm_hist_kernel(const float* __restrict__ x, const float* __restrict__ t,
                long long n) {
    __shared__ unsigned int sh[BINS * 33];
    const int tid = threadIdx.x;
    for (int i = tid; i < BINS * 33; i += blockDim.x) sh[i] = 0u;
    __syncthreads();

    const int lane = tid & 31;
    const long long nv = n >> 3;  // units of 8 floats (2 x float4)
    const long long gstride = (long long)gridDim.x * blockDim.x;
    const float4* __restrict__ x4 = (const float4*)x;
    const float4* __restrict__ t4 = (const float4*)t;

    for (long long i = (long long)blockIdx.x * blockDim.x + tid; i < nv; i += gstride) {
        float4 xa = x4[2 * i],     ta = t4[2 * i];
        float4 xb = x4[2 * i + 1], tb = t4[2 * i + 1];
        atomicAdd(&sh[bin_of(xa.x, ta.x) * 33 + lane], 1u);
        atomicAdd(&sh[bin_of(xa.y, ta.y) * 33 + lane], 1u);
        atomicAdd(&sh[bin_of(xa.z, ta.z) * 33 + lane], 1u);
        atomicAdd(&sh[bin_of(xa.w, ta.w) * 33 + lane], 1u);
        atomicAdd(&sh[bin_of(xb.x, tb.x) * 33 + lane], 1u);
        atomicAdd(&sh[bin_of(xb.y, tb.y) * 33 + lane], 1u);
        atomicAdd(&sh[bin_of(xb.z, tb.z) * 33 + lane], 1u);
        atomicAdd(&sh[bin_of(xb.w, tb.w) * 33 + lane], 1u);
    }
    // scalar tail (n not divisible by 8)
    for (long long i = nv * 8 + (long long)blockIdx.x * blockDim.x + tid; i < n; i += gstride) {
        atomicAdd(&sh[bin_of(x[i], t[i]) * 33 + lane], 1u);
    }
    __syncthreads();

    // Reduce 10 rows x 32 lanes -> 10 global atomics per block.
    if (tid < BINS * 32) {
        const int row = tid >> 5;
        unsigned int v = sh[row * 33 + (tid & 31)];
        #pragma unroll
        for (int o = 16; o > 0; o >>= 1) v += __shfl_down_sync(0xffffffffu, v, o);
        if ((tid & 31) == 0) atomicAdd(&g_counts[row], v);
    }
}

// ---------------------------------------------------------------------------
// Pass 2: out[i] = bce(x,t) / (counts[idx] * n_nonempty_bins)
// Per-bin factor recomputed per block from g_counts (10 loads; deterministic).
// ---------------------------------------------------------------------------
__global__ void __launch_bounds__(512)
ghm_out_kernel(const float* __restrict__ x, const float* __restrict__ t,
               float* __restrict__ out, long long n) {
    __shared__ float sf[BINS];
    if (threadIdx.x < 32) {
        unsigned int c = (threadIdx.x < BINS) ? g_counts[threadIdx.x] : 0u;
        unsigned int m = __ballot_sync(0xffffffffu, c > 0u);
        float nb = (float)max(__popc(m), 1);
        if (threadIdx.x < BINS)
            sf[threadIdx.x] = (c > 0u) ? __fdividef(1.0f, (float)c * nb) : 0.0f;
    }
    __syncthreads();

    const long long nv = n >> 3;
    const long long gstride = (long long)gridDim.x * blockDim.x;
    const float4* __restrict__ x4 = (const float4*)x;
    const float4* __restrict__ t4 = (const float4*)t;
    float4* __restrict__ o4 = (float4*)out;

    for (long long i = (long long)blockIdx.x * blockDim.x + threadIdx.x; i < nv; i += gstride) {
        float4 xa = x4[2 * i],     ta = t4[2 * i];
        float4 xb = x4[2 * i + 1], tb = t4[2 * i + 1];
        float4 ra, rb;
        ra.x = bce_of(xa.x, ta.x) * sf[bin_of(xa.x, ta.x)];
        ra.y = bce_of(xa.y, ta.y) * sf[bin_of(xa.y, ta.y)];
        ra.z = bce_of(xa.z, ta.z) * sf[bin_of(xa.z, ta.z)];
        ra.w = bce_of(xa.w, ta.w) * sf[bin_of(xa.w, ta.w)];
        rb.x = bce_of(xb.x, tb.x) * sf[bin_of(xb.x, tb.x)];
        rb.y = bce_of(xb.y, tb.y) * sf[bin_of(xb.y, tb.y)];
        rb.z = bce_of(xb.z, tb.z) * sf[bin_of(xb.z, tb.z)];
        rb.w = bce_of(xb.w, tb.w) * sf[bin_of(xb.w, tb.w)];
        o4[2 * i]     = ra;
        o4[2 * i + 1] = rb;
    }
    for (long long i = nv * 8 + (long long)blockIdx.x * blockDim.x + threadIdx.x; i < n; i += gstride) {
        float xv = x[i], tv = t[i];
        out[i] = bce_of(xv, tv) * sf[bin_of(xv, tv)];
    }
}

extern "C" void kernel_launch(void* const* d_in, const int* in_sizes, int n_in,
                              void* d_out, int out_size) {
    const float* x = (const float*)d_in[0];
    const float* t = (const float*)d_in[1];
    float* out = (float*)d_out;
    long long n = (long long)in_sizes[0];

    const int threads = 512;
    const int blocks = 148 * 4;  // persistent-style grid-stride; works for any SM count

    ghm_init_kernel<<<1, 32>>>();
    ghm_hist_kernel<<<blocks, threads>>>(x, t, n);
    ghm_out_kernel<<<blocks, threads>>>(x, t, out, n);
}

// round 7
// speedup vs baseline: 1.0617x; 1.0617x over previous
#include <cuda_runtime.h>

#define BINS    10
#define THREADS 512
#define BLOCKS  296   // 148 SMs x 2 resident blocks (enforced by __launch_bounds__)

// Scratch: global histogram counts (integer => deterministic, exact) + arrival
// counter for the self-cleaning epilogue. Zero-initialized at module load;
// the out kernel restores both to zero every run => graph-replay safe.
__device__ unsigned int g_counts[BINS];
__device__ unsigned int g_done;

__device__ __forceinline__ int bin_of(float x, float t) {
    // EXACT same math as the validated kernel (rel_err 7.6e-8): do not perturb.
    float p = __fdividef(1.0f, 1.0f + __expf(-x));
    float g = fabsf(p - t);
    int idx = (int)(g * 10.0f);   // g >= 0, trunc == floor
    return idx > (BINS - 1) ? (BINS - 1) : idx;
}

__device__ __forceinline__ float bce_of(float x, float t) {
    // stable BCE-with-logits: max(x,0) - x*t + log1p(exp(-|x|))
    return fmaxf(x, 0.0f) - x * t + __logf(1.0f + __expf(-fabsf(x)));
}

// ---------------------------------------------------------------------------
// Pass 1: histogram, ASCENDING order (leaves the array tail hot in L2 for
// pass 2). Lane-spread sub-histograms sh[bin*33 + lane]: all 32 lanes of a
// warp hit distinct addresses -> zero intra-warp same-address serialization.
// Paired-coalesced float4 indexing: every LDG.128 is fully contiguous.
// ---------------------------------------------------------------------------
__global__ void __launch_bounds__(THREADS, 2)
ghm_hist_kernel(const float* __restrict__ x, const float* __restrict__ t,
                long long n) {
    __shared__ unsigned int sh[BINS * 33];
    const int tid = threadIdx.x;
    for (int i = tid; i < BINS * 33; i += THREADS) sh[i] = 0u;
    __syncthreads();

    const int lane = tid & 31;
    const long long n4      = n >> 2;                               // float4 count
    const long long per_it  = (long long)gridDim.x * (THREADS * 2); // f4 per grid-iter
    const long long full_its = n4 / per_it;
    const long long blk_base = (long long)blockIdx.x * (THREADS * 2) + tid;
    const float4* __restrict__ x4 = (const float4*)x;
    const float4* __restrict__ t4 = (const float4*)t;

    for (long long it = 0; it < full_its; ++it) {
        const long long i0 = it * per_it + blk_base;
        const long long i1 = i0 + THREADS;
        float4 xa = x4[i0], ta = t4[i0];
        float4 xb = x4[i1], tb = t4[i1];
        atomicAdd(&sh[bin_of(xa.x, ta.x) * 33 + lane], 1u);
        atomicAdd(&sh[bin_of(xa.y, ta.y) * 33 + lane], 1u);
        atomicAdd(&sh[bin_of(xa.z, ta.z) * 33 + lane], 1u);
        atomicAdd(&sh[bin_of(xa.w, ta.w) * 33 + lane], 1u);
        atomicAdd(&sh[bin_of(xb.x, tb.x) * 33 + lane], 1u);
        atomicAdd(&sh[bin_of(xb.y, tb.y) * 33 + lane], 1u);
        atomicAdd(&sh[bin_of(xb.z, tb.z) * 33 + lane], 1u);
        atomicAdd(&sh[bin_of(xb.w, tb.w) * 33 + lane], 1u);
    }

    const long long gtid     = (long long)blockIdx.x * THREADS + tid;
    const long long gthreads = (long long)gridDim.x * THREADS;
    // remainder float4s
    for (long long i = full_its * per_it + gtid; i < n4; i += gthreads) {
        float4 xa = x4[i], ta = t4[i];
        atomicAdd(&sh[bin_of(xa.x, ta.x) * 33 + lane], 1u);
        atomicAdd(&sh[bin_of(xa.y, ta.y) * 33 + lane], 1u);
        atomicAdd(&sh[bin_of(xa.z, ta.z) * 33 + lane], 1u);
        atomicAdd(&sh[bin_of(xa.w, ta.w) * 33 + lane], 1u);
    }
    // scalar tail (n % 4)
    for (long long i = (n4 << 2) + gtid; i < n; i += gthreads)
        atomicAdd(&sh[bin_of(x[i], t[i]) * 33 + lane], 1u);

    __syncthreads();
    // Reduce 10 rows x 32 lanes -> 10 global integer atomics per block.
    if (tid < BINS * 32) {
        const int row = tid >> 5;
        unsigned int v = sh[row * 33 + (tid & 31)];
        #pragma unroll
        for (int o = 16; o > 0; o >>= 1) v += __shfl_down_sync(0xffffffffu, v, o);
        if ((tid & 31) == 0) atomicAdd(&g_counts[row], v);
    }
}

// ---------------------------------------------------------------------------
// Pass 2: out[i] = bce(x,t) / (counts[idx] * n_nonempty), DESCENDING order so
// the first reads hit pass-1's L2 tail. __ldcs/__stcs (evict-first): x, t and
// out are dead after this pass, keep them from evicting the reusable window.
// Epilogue: last block to arrive zeroes g_counts/g_done for the next replay.
// ---------------------------------------------------------------------------
__global__ void __launch_bounds__(THREADS, 2)
ghm_out_kernel(const float* __restrict__ x, const float* __restrict__ t,
               float* __restrict__ out, long long n) {
    __shared__ float sf[BINS];
    const int tid = threadIdx.x;
    if (tid < 32) {
        unsigned int c = (tid < BINS) ? g_counts[tid] : 0u;
        unsigned int m = __ballot_sync(0xffffffffu, c > 0u);
        float nb = (float)max(__popc(m), 1);
        if (tid < BINS)
            sf[tid] = (c > 0u) ? __fdividef(1.0f, (float)c * nb) : 0.0f;
    }
    __syncthreads();

    // Self-cleaning: every block has now READ g_counts. The last of the
    // gridDim.x arrivals (strictly after all reads) resets the scratch state,
    // making kernel_launch deterministic across graph replays with no init
    // kernel. Runs concurrently with the main loop below.
    if (tid == 0) {
        __threadfence();
        if (atomicAdd(&g_done, 1u) == (unsigned)gridDim.x - 1u) {
            #pragma unroll
            for (int b = 0; b < BINS; ++b) g_counts[b] = 0u;
            __threadfence();
            g_done = 0u;
        }
    }

    const long long n4      = n >> 2;
    const long long per_it  = (long long)gridDim.x * (THREADS * 2);
    const long long full_its = n4 / per_it;
    const long long blk_base = (long long)blockIdx.x * (THREADS * 2) + tid;
    const long long gtid     = (long long)blockIdx.x * THREADS + tid;
    const long long gthreads = (long long)gridDim.x * THREADS;
    const float4* __restrict__ x4 = (const float4*)x;
    const float4* __restrict__ t4 = (const float4*)t;
    float4* __restrict__ o4 = (float4*)out;

    // Highest addresses first: scalar tail, then remainder float4s...
    for (long long i = (n4 << 2) + gtid; i < n; i += gthreads) {
        float xv = x[i], tv = t[i];
        out[i] = bce_of(xv, tv) * sf[bin_of(xv, tv)];
    }
    for (long long i = full_its * per_it + gtid; i < n4; i += gthreads) {
        float4 xa = __ldcs(&x4[i]), ta = __ldcs(&t4[i]);
        float4 ra;
        ra.x = bce_of(xa.x, ta.x) * sf[bin_of(xa.x, ta.x)];
        ra.y = bce_of(xa.y, ta.y) * sf[bin_of(xa.y, ta.y)];
        ra.z = bce_of(xa.z, ta.z) * sf[bin_of(xa.z, ta.z)];
        ra.w = bce_of(xa.w, ta.w) * sf[bin_of(xa.w, ta.w)];
        __stcs(&o4[i], ra);
    }
    // ...then the main region in DESCENDING grid-iteration order.
    for (long long it = full_its - 1; it >= 0; --it) {
        const long long i0 = it * per_it + blk_base;
        const long long i1 = i0 + THREADS;
        float4 xa = __ldcs(&x4[i0]), ta = __ldcs(&t4[i0]);
        float4 xb = __ldcs(&x4[i1]), tb = __ldcs(&t4[i1]);
        float4 ra, rb;
        ra.x = bce_of(xa.x, ta.x) * sf[bin_of(xa.x, ta.x)];
        ra.y = bce_of(xa.y, ta.y) * sf[bin_of(xa.y, ta.y)];
        ra.z = bce_of(xa.z, ta.z) * sf[bin_of(xa.z, ta.z)];
        ra.w = bce_of(xa.w, ta.w) * sf[bin_of(xa.w, ta.w)];
        rb.x = bce_of(xb.x, tb.x) * sf[bin_of(xb.x, tb.x)];
        rb.y = bce_of(xb.y, tb.y) * sf[bin_of(xb.y, tb.y)];
        rb.z = bce_of(xb.z, tb.z) * sf[bin_of(xb.z, tb.z)];
        rb.w = bce_of(xb.w, tb.w) * sf[bin_of(xb.w, tb.w)];
        __stcs(&o4[i0], ra);
        __stcs(&o4[i1], rb);
    }
}

extern "C" void kernel_launch(void* const* d_in, const int* in_sizes, int n_in,
                              void* d_out, int out_size) {
    const float* x = (const float*)d_in[0];
    const float* t = (const float*)d_in[1];
    float* out = (float*)d_out;
    long long n = (long long)in_sizes[0];

    ghm_hist_kernel<<<BLOCKS, THREADS>>>(x, t, n);
    ghm_out_kernel<<<BLOCKS, THREADS>>>(x, t, out, n);
}